// round 1
// baseline (speedup 1.0000x reference)
#include <cuda_runtime.h>
#include <cuda_bf16.h>

#define N_NODES 50000
#define N_EDGES 800000
#define D_IN 96
#define HID 128

// ---------------- scratch (device globals; no allocation allowed) ----------------
__device__ __align__(16) float g_buf0[N_NODES * HID];
__device__ __align__(16) float g_buf1[N_NODES * HID];
__device__ __align__(16) float g_buf2[N_NODES * HID];
__device__ float g_dinv[N_NODES];
__device__ int   g_deg[N_NODES];
__device__ int   g_rowptr[N_NODES + 1];
__device__ int   g_cursor[N_NODES];
__device__ int   g_csr_src[N_EDGES];
__device__ float g_csr_norm[N_EDGES];

// ---------------- small graph kernels ----------------
__global__ void zero_deg_kernel() {
    int i = blockIdx.x * blockDim.x + threadIdx.x;
    if (i < N_NODES) g_deg[i] = 0;
}

__global__ void hist_kernel(const int* __restrict__ dst) {
    int e = blockIdx.x * blockDim.x + threadIdx.x;
    if (e < N_EDGES) atomicAdd(&g_deg[dst[e]], 1);
}

__global__ void dinv_kernel() {
    int i = blockIdx.x * blockDim.x + threadIdx.x;
    if (i < N_NODES) g_dinv[i] = rsqrtf((float)(g_deg[i] + 1));  // +1 self loop
}

// single-block shuffle-based exclusive scan of g_deg -> g_rowptr, g_cursor
__global__ void scan_kernel() {
    __shared__ int warp_sums[32];
    __shared__ int s_carry;
    int tid = threadIdx.x, lane = tid & 31, wid = tid >> 5;
    if (tid == 0) s_carry = 0;
    __syncthreads();
    for (int base = 0; base < N_NODES; base += 1024) {
        int idx = base + tid;
        int v = (idx < N_NODES) ? g_deg[idx] : 0;
        int x = v;
        #pragma unroll
        for (int off = 1; off < 32; off <<= 1) {
            int t = __shfl_up_sync(0xffffffff, x, off);
            if (lane >= off) x += t;
        }
        if (lane == 31) warp_sums[wid] = x;
        __syncthreads();
        if (wid == 0) {
            int ws = warp_sums[lane];
            #pragma unroll
            for (int off = 1; off < 32; off <<= 1) {
                int t = __shfl_up_sync(0xffffffff, ws, off);
                if (lane >= off) ws += t;
            }
            warp_sums[lane] = ws;
        }
        __syncthreads();
        int warp_off = (wid == 0) ? 0 : warp_sums[wid - 1];
        int excl = s_carry + warp_off + x - v;
        if (idx < N_NODES) { g_rowptr[idx] = excl; g_cursor[idx] = excl; }
        __syncthreads();
        if (tid == 1023) s_carry += warp_sums[31];
        __syncthreads();
    }
    if (threadIdx.x == 0) g_rowptr[N_NODES] = s_carry;
}

__global__ void fill_kernel(const int* __restrict__ src, const int* __restrict__ dst) {
    int e = blockIdx.x * blockDim.x + threadIdx.x;
    if (e < N_EDGES) {
        int s = src[e], d = dst[e];
        int p = atomicAdd(&g_cursor[d], 1);
        g_csr_src[p]  = s;
        g_csr_norm[p] = g_dinv[s] * g_dinv[d];
    }
}

// ---------------- fp32 register-tiled GEMM: C = act(A[M,K] @ W[K,128] (+bias)) ----------------
#define BM 128
#define BN 128
#define BK 16
#define TM 8
#define TN 8

__global__ __launch_bounds__(256, 2)
void gemm_kernel(const float* __restrict__ A, const float* __restrict__ W,
                 const float* __restrict__ bias, float* __restrict__ C,
                 int M, int K, int do_relu) {
    __shared__ float As[BK][BM + 4];
    __shared__ float Ws[BK][BN];
    const int m0 = blockIdx.x * BM;
    const int tid = threadIdx.x;
    const int tx = tid & 15;   // col group: cols tx*8 .. tx*8+7
    const int ty = tid >> 4;   // row group: rows ty*8 .. ty*8+7

    float acc[TM][TN];
    #pragma unroll
    for (int i = 0; i < TM; i++)
        #pragma unroll
        for (int j = 0; j < TN; j++) acc[i][j] = 0.f;

    const int akk = (tid & 3) * 4;   // k offset within tile for A load
    const int ar  = tid >> 2;        // row 0..63 (+64)
    const int wr  = tid >> 5;        // 0..7 (+8)
    const int wc  = (tid & 31) * 4;

    for (int k0 = 0; k0 < K; k0 += BK) {
        #pragma unroll
        for (int rr = 0; rr < 2; rr++) {
            int row = m0 + ar + rr * 64;
            float4 v = make_float4(0.f, 0.f, 0.f, 0.f);
            if (row < M) v = *(const float4*)&A[(long)row * K + k0 + akk];
            As[akk + 0][ar + rr * 64] = v.x;
            As[akk + 1][ar + rr * 64] = v.y;
            As[akk + 2][ar + rr * 64] = v.z;
            As[akk + 3][ar + rr * 64] = v.w;
        }
        #pragma unroll
        for (int rr = 0; rr < 2; rr++) {
            int krow = k0 + wr + rr * 8;
            *(float4*)&Ws[wr + rr * 8][wc] = *(const float4*)&W[(long)krow * BN + wc];
        }
        __syncthreads();
        #pragma unroll
        for (int k = 0; k < BK; k++) {
            float a[TM], w[TN];
            #pragma unroll
            for (int i = 0; i < TM; i++) a[i] = As[k][ty * TM + i];
            #pragma unroll
            for (int j = 0; j < TN; j++) w[j] = Ws[k][tx * TN + j];
            #pragma unroll
            for (int i = 0; i < TM; i++)
                #pragma unroll
                for (int j = 0; j < TN; j++)
                    acc[i][j] += a[i] * w[j];
        }
        __syncthreads();
    }

    #pragma unroll
    for (int i = 0; i < TM; i++) {
        int row = m0 + ty * TM + i;
        if (row >= M) continue;
        #pragma unroll
        for (int j = 0; j < TN; j += 4) {
            int col = tx * TN + j;
            float4 v = make_float4(acc[i][j], acc[i][j + 1], acc[i][j + 2], acc[i][j + 3]);
            if (bias) {
                v.x += bias[col]; v.y += bias[col + 1];
                v.z += bias[col + 2]; v.w += bias[col + 3];
            }
            if (do_relu) {
                v.x = fmaxf(v.x, 0.f); v.y = fmaxf(v.y, 0.f);
                v.z = fmaxf(v.z, 0.f); v.w = fmaxf(v.w, 0.f);
            }
            *(float4*)&C[(long)row * BN + col] = v;
        }
    }
}

// ---------------- GCN aggregation: warp per node, gather over CSR ----------------
__global__ void agg_kernel(const float* __restrict__ xw, const float* __restrict__ bias,
                           float* __restrict__ out) {
    int warp = (blockIdx.x * blockDim.x + threadIdx.x) >> 5;
    int lane = threadIdx.x & 31;
    if (warp >= N_NODES) return;
    const float4* xw4 = (const float4*)xw;
    float di = g_dinv[warp];
    float sl = di * di;                       // self-loop norm
    float4 v = xw4[warp * 32 + lane];
    float4 acc = make_float4(v.x * sl, v.y * sl, v.z * sl, v.w * sl);
    int p    = g_rowptr[warp];
    int pend = g_rowptr[warp + 1];
    for (; p < pend; p++) {
        int s = g_csr_src[p];
        float nm = g_csr_norm[p];
        float4 u = xw4[s * 32 + lane];
        acc.x += u.x * nm; acc.y += u.y * nm;
        acc.z += u.z * nm; acc.w += u.w * nm;
    }
    float4 b = ((const float4*)bias)[lane];
    acc.x = fmaxf(acc.x + b.x, 0.f);
    acc.y = fmaxf(acc.y + b.y, 0.f);
    acc.z = fmaxf(acc.z + b.z, 0.f);
    acc.w = fmaxf(acc.w + b.w, 0.f);
    ((float4*)out)[warp * 32 + lane] = acc;
}

// ---------------- edge MLP: warp per edge; A includes bm1 ----------------
__global__ void edge_kernel(const float* __restrict__ Aarr, const float* __restrict__ Barr,
                            const int* __restrict__ src, const int* __restrict__ dst,
                            const float* __restrict__ Wm2, const float* __restrict__ bm2,
                            float* __restrict__ out) {
    int warp = (blockIdx.x * blockDim.x + threadIdx.x) >> 5;
    int lane = threadIdx.x & 31;
    if (warp >= N_EDGES) return;
    int s = src[warp], d = dst[warp];
    float4 a = ((const float4*)Aarr)[s * 32 + lane];
    float4 b = ((const float4*)Barr)[d * 32 + lane];
    float4 w = ((const float4*)Wm2)[lane];
    float h0 = fmaxf(a.x + b.x, 0.f);
    float h1 = fmaxf(a.y + b.y, 0.f);
    float h2 = fmaxf(a.z + b.z, 0.f);
    float h3 = fmaxf(a.w + b.w, 0.f);
    float sum = h0 * w.x + h1 * w.y + h2 * w.z + h3 * w.w;
    #pragma unroll
    for (int off = 16; off > 0; off >>= 1)
        sum += __shfl_down_sync(0xffffffff, sum, off);
    if (lane == 0) out[warp] = sum + bm2[0];
}

// ---------------- launch ----------------
extern "C" void kernel_launch(void* const* d_in, const int* in_sizes, int n_in,
                              void* d_out, int out_size) {
    const float* x      = (const float*)d_in[0];
    const int*   eidx   = (const int*)d_in[1];
    const float* W_in   = (const float*)d_in[2];
    const float* b_in   = (const float*)d_in[3];
    const float* W1     = (const float*)d_in[4];
    const float* b1     = (const float*)d_in[5];
    const float* W2     = (const float*)d_in[6];
    const float* b2     = (const float*)d_in[7];
    const float* Wm1    = (const float*)d_in[8];
    const float* bm1    = (const float*)d_in[9];
    const float* Wm2    = (const float*)d_in[10];
    const float* bm2    = (const float*)d_in[11];
    float* out = (float*)d_out;

    const int* src = eidx;
    const int* dst = eidx + N_EDGES;

    float *buf0, *buf1, *buf2;
    cudaGetSymbolAddress((void**)&buf0, g_buf0);
    cudaGetSymbolAddress((void**)&buf1, g_buf1);
    cudaGetSymbolAddress((void**)&buf2, g_buf2);

    const int TPB = 256;
    dim3 nodeGrid((N_NODES + TPB - 1) / TPB);
    dim3 edgeGrid((N_EDGES + TPB - 1) / TPB);
    dim3 gemmGrid((N_NODES + BM - 1) / BM);
    dim3 aggGrid((N_NODES * 32 + TPB - 1) / TPB);
    dim3 emlpGrid(((long)N_EDGES * 32 + TPB - 1) / TPB);

    // graph preprocessing (CSR by dst, reused by both convs)
    zero_deg_kernel<<<nodeGrid, TPB>>>();
    hist_kernel<<<edgeGrid, TPB>>>(dst);
    dinv_kernel<<<nodeGrid, TPB>>>();
    scan_kernel<<<1, 1024>>>();
    fill_kernel<<<edgeGrid, TPB>>>(src, dst);

    // h0 = relu(x @ W_in + b_in)            -> buf0
    gemm_kernel<<<gemmGrid, 256>>>(x, W_in, b_in, buf0, N_NODES, D_IN, 1);
    // xw1 = h0 @ W1                          -> buf1
    gemm_kernel<<<gemmGrid, 256>>>(buf0, W1, nullptr, buf1, N_NODES, HID, 0);
    // h1 = relu(agg(xw1) + b1)               -> buf2
    agg_kernel<<<aggGrid, TPB>>>(buf1, b1, buf2);
    // xw2 = h1 @ W2                          -> buf0
    gemm_kernel<<<gemmGrid, 256>>>(buf2, W2, nullptr, buf0, N_NODES, HID, 0);
    // h2 = relu(agg(xw2) + b2)               -> buf1
    agg_kernel<<<aggGrid, TPB>>>(buf0, b2, buf1);
    // A = h2 @ Wm1[:128] + bm1               -> buf0
    gemm_kernel<<<gemmGrid, 256>>>(buf1, Wm1, bm1, buf0, N_NODES, HID, 0);
    // B = h2 @ Wm1[128:]                     -> buf2
    gemm_kernel<<<gemmGrid, 256>>>(buf1, Wm1 + HID * HID, nullptr, buf2, N_NODES, HID, 0);
    // logits per edge
    edge_kernel<<<emlpGrid, TPB>>>(buf0, buf2, src, dst, Wm2, bm2, out);
}

// round 2
// speedup vs baseline: 1.2527x; 1.2527x over previous
#include <cuda_runtime.h>
#include <cuda_bf16.h>

#define N_NODES 50000
#define N_EDGES 800000
#define D_IN 96
#define HID 128
#define SCAN_TPB 1024
#define SCAN_BLOCKS ((N_NODES + SCAN_TPB - 1) / SCAN_TPB)   // 49

// ---------------- scratch (device globals; no allocation allowed) ----------------
__device__ __align__(16) float g_buf0[N_NODES * HID];
__device__ __align__(16) float g_buf1[N_NODES * HID];
__device__ __align__(16) float g_buf2[N_NODES * HID];
__device__ float g_dinv[N_NODES];
__device__ int   g_deg[N_NODES];
__device__ int   g_rowptr[N_NODES + 1];
__device__ int   g_cursor[N_NODES];
__device__ int   g_partials[SCAN_BLOCKS + 1];
__device__ int   g_csr_src[N_EDGES];
__device__ int   g_csr_eid[N_EDGES];
__device__ float g_csr_norm[N_EDGES];

// ---------------- graph preprocessing ----------------
__global__ void zero_deg_kernel() {
    int i = blockIdx.x * blockDim.x + threadIdx.x;
    if (i < N_NODES) g_deg[i] = 0;
}

__global__ void hist_kernel(const int* __restrict__ dst) {
    int e = blockIdx.x * blockDim.x + threadIdx.x;
    if (e < N_EDGES) atomicAdd(&g_deg[dst[e]], 1);
}

// pass 1: per-block exclusive scan of deg -> rowptr (local), block sums -> partials.
// Also computes dinv (reads deg anyway).
__global__ void scan1_kernel() {
    __shared__ int ws[32];
    int gid = blockIdx.x * SCAN_TPB + threadIdx.x;
    int lane = threadIdx.x & 31, wid = threadIdx.x >> 5;
    int v = (gid < N_NODES) ? g_deg[gid] : 0;
    if (gid < N_NODES) g_dinv[gid] = rsqrtf((float)(v + 1));  // +1 self loop
    int x = v;
    #pragma unroll
    for (int off = 1; off < 32; off <<= 1) {
        int t = __shfl_up_sync(0xffffffff, x, off);
        if (lane >= off) x += t;
    }
    if (lane == 31) ws[wid] = x;
    __syncthreads();
    if (wid == 0) {
        int t = ws[lane];
        #pragma unroll
        for (int off = 1; off < 32; off <<= 1) {
            int u = __shfl_up_sync(0xffffffff, t, off);
            if (lane >= off) t += u;
        }
        ws[lane] = t;   // inclusive warp-sum scan
    }
    __syncthreads();
    int excl = (wid ? ws[wid - 1] : 0) + x - v;
    if (gid < N_NODES) g_rowptr[gid] = excl;
    if (threadIdx.x == 0) g_partials[blockIdx.x] = ws[31];
}

// pass 2: exclusive scan of the 49 block sums (trivially small)
__global__ void scan2_kernel() {
    if (threadIdx.x == 0) {
        int run = 0;
        for (int i = 0; i < SCAN_BLOCKS; i++) {
            int v = g_partials[i];
            g_partials[i] = run;
            run += v;
        }
        g_rowptr[N_NODES] = run;
    }
}

// pass 3: add block offsets, init cursor
__global__ void scan3_kernel() {
    int gid = blockIdx.x * SCAN_TPB + threadIdx.x;
    if (gid < N_NODES) {
        int r = g_rowptr[gid] + g_partials[blockIdx.x];
        g_rowptr[gid] = r;
        g_cursor[gid] = r;
    }
}

__global__ void fill_kernel(const int* __restrict__ src, const int* __restrict__ dst) {
    int e = blockIdx.x * blockDim.x + threadIdx.x;
    if (e < N_EDGES) {
        int s = src[e], d = dst[e];
        int p = atomicAdd(&g_cursor[d], 1);
        g_csr_src[p]  = s;
        g_csr_eid[p]  = e;
        g_csr_norm[p] = g_dinv[s] * g_dinv[d];
    }
}

// ---------------- fp32 register-tiled GEMM: C = act(A[M,K] @ W[K,128] (+bias)) ----------------
#define BM 128
#define BN 128
#define BK 16
#define TM 8
#define TN 8

__global__ __launch_bounds__(256, 2)
void gemm_kernel(const float* __restrict__ A, const float* __restrict__ W,
                 const float* __restrict__ bias, float* __restrict__ C,
                 int M, int K, int do_relu) {
    __shared__ float As[BK][BM + 4];
    __shared__ float Ws[BK][BN];
    const int m0 = blockIdx.x * BM;
    const int tid = threadIdx.x;
    const int tx = tid & 15;
    const int ty = tid >> 4;

    float acc[TM][TN];
    #pragma unroll
    for (int i = 0; i < TM; i++)
        #pragma unroll
        for (int j = 0; j < TN; j++) acc[i][j] = 0.f;

    const int akk = (tid & 3) * 4;
    const int ar  = tid >> 2;
    const int wr  = tid >> 5;
    const int wc  = (tid & 31) * 4;

    for (int k0 = 0; k0 < K; k0 += BK) {
        #pragma unroll
        for (int rr = 0; rr < 2; rr++) {
            int row = m0 + ar + rr * 64;
            float4 v = make_float4(0.f, 0.f, 0.f, 0.f);
            if (row < M) v = *(const float4*)&A[(long)row * K + k0 + akk];
            As[akk + 0][ar + rr * 64] = v.x;
            As[akk + 1][ar + rr * 64] = v.y;
            As[akk + 2][ar + rr * 64] = v.z;
            As[akk + 3][ar + rr * 64] = v.w;
        }
        #pragma unroll
        for (int rr = 0; rr < 2; rr++) {
            int krow = k0 + wr + rr * 8;
            *(float4*)&Ws[wr + rr * 8][wc] = *(const float4*)&W[(long)krow * BN + wc];
        }
        __syncthreads();
        #pragma unroll
        for (int k = 0; k < BK; k++) {
            float a[TM], w[TN];
            #pragma unroll
            for (int i = 0; i < TM; i++) a[i] = As[k][ty * TM + i];
            #pragma unroll
            for (int j = 0; j < TN; j++) w[j] = Ws[k][tx * TN + j];
            #pragma unroll
            for (int i = 0; i < TM; i++)
                #pragma unroll
                for (int j = 0; j < TN; j++)
                    acc[i][j] += a[i] * w[j];
        }
        __syncthreads();
    }

    #pragma unroll
    for (int i = 0; i < TM; i++) {
        int row = m0 + ty * TM + i;
        if (row >= M) continue;
        #pragma unroll
        for (int j = 0; j < TN; j += 4) {
            int col = tx * TN + j;
            float4 v = make_float4(acc[i][j], acc[i][j + 1], acc[i][j + 2], acc[i][j + 3]);
            if (bias) {
                v.x += bias[col]; v.y += bias[col + 1];
                v.z += bias[col + 2]; v.w += bias[col + 3];
            }
            if (do_relu) {
                v.x = fmaxf(v.x, 0.f); v.y = fmaxf(v.y, 0.f);
                v.z = fmaxf(v.z, 0.f); v.w = fmaxf(v.w, 0.f);
            }
            *(float4*)&C[(long)row * BN + col] = v;
        }
    }
}

// ---------------- GCN aggregation: warp per node, gather over CSR ----------------
__global__ void agg_kernel(const float* __restrict__ xw, const float* __restrict__ bias,
                           float* __restrict__ out) {
    int warp = (blockIdx.x * blockDim.x + threadIdx.x) >> 5;
    int lane = threadIdx.x & 31;
    if (warp >= N_NODES) return;
    const float4* xw4 = (const float4*)xw;
    float di = g_dinv[warp];
    float sl = di * di;
    float4 v = xw4[warp * 32 + lane];
    float4 acc = make_float4(v.x * sl, v.y * sl, v.z * sl, v.w * sl);
    int p    = g_rowptr[warp];
    int pend = g_rowptr[warp + 1];
    for (; p < pend; p++) {
        int s = g_csr_src[p];
        float nm = g_csr_norm[p];
        float4 u = xw4[s * 32 + lane];
        acc.x += u.x * nm; acc.y += u.y * nm;
        acc.z += u.z * nm; acc.w += u.w * nm;
    }
    float4 b = ((const float4*)bias)[lane];
    acc.x = fmaxf(acc.x + b.x, 0.f);
    acc.y = fmaxf(acc.y + b.y, 0.f);
    acc.z = fmaxf(acc.z + b.z, 0.f);
    acc.w = fmaxf(acc.w + b.w, 0.f);
    ((float4*)out)[warp * 32 + lane] = acc;
}

// ---------------- edge MLP: warp per dst-node over CSR; B[d] stays in registers ----------------
__global__ void edge_kernel(const float* __restrict__ Aarr, const float* __restrict__ Barr,
                            const float* __restrict__ Wm2, const float* __restrict__ bm2,
                            float* __restrict__ out) {
    int node = (blockIdx.x * blockDim.x + threadIdx.x) >> 5;
    int lane = threadIdx.x & 31;
    if (node >= N_NODES) return;
    int p    = g_rowptr[node];
    int pend = g_rowptr[node + 1];
    if (p == pend) return;
    float4 b = ((const float4*)Barr)[node * 32 + lane];
    float4 w = ((const float4*)Wm2)[lane];
    float bm = bm2[0];
    for (; p < pend; p++) {
        int s   = g_csr_src[p];
        int eid = g_csr_eid[p];
        float4 a = ((const float4*)Aarr)[s * 32 + lane];
        float sum = fmaxf(a.x + b.x, 0.f) * w.x
                  + fmaxf(a.y + b.y, 0.f) * w.y
                  + fmaxf(a.z + b.z, 0.f) * w.z
                  + fmaxf(a.w + b.w, 0.f) * w.w;
        #pragma unroll
        for (int off = 16; off > 0; off >>= 1)
            sum += __shfl_down_sync(0xffffffff, sum, off);
        if (lane == 0) out[eid] = sum + bm;
    }
}

// ---------------- launch ----------------
extern "C" void kernel_launch(void* const* d_in, const int* in_sizes, int n_in,
                              void* d_out, int out_size) {
    const float* x      = (const float*)d_in[0];
    const int*   eidx   = (const int*)d_in[1];
    const float* W_in   = (const float*)d_in[2];
    const float* b_in   = (const float*)d_in[3];
    const float* W1     = (const float*)d_in[4];
    const float* b1     = (const float*)d_in[5];
    const float* W2     = (const float*)d_in[6];
    const float* b2     = (const float*)d_in[7];
    const float* Wm1    = (const float*)d_in[8];
    const float* bm1    = (const float*)d_in[9];
    const float* Wm2    = (const float*)d_in[10];
    const float* bm2    = (const float*)d_in[11];
    float* out = (float*)d_out;

    const int* src = eidx;
    const int* dst = eidx + N_EDGES;

    float *buf0, *buf1, *buf2;
    cudaGetSymbolAddress((void**)&buf0, g_buf0);
    cudaGetSymbolAddress((void**)&buf1, g_buf1);
    cudaGetSymbolAddress((void**)&buf2, g_buf2);

    // one-time side stream + fork/join events (resource creation only; no device alloc)
    static cudaStream_t s2 = nullptr;
    static cudaEvent_t evF = nullptr, evJ = nullptr;
    if (!s2) {
        cudaStreamCreateWithFlags(&s2, cudaStreamNonBlocking);
        cudaEventCreateWithFlags(&evF, cudaEventDisableTiming);
        cudaEventCreateWithFlags(&evJ, cudaEventDisableTiming);
    }

    const int TPB = 256;
    dim3 nodeGrid((N_NODES + TPB - 1) / TPB);
    dim3 edgeGrid((N_EDGES + TPB - 1) / TPB);
    dim3 gemmGrid((N_NODES + BM - 1) / BM);
    dim3 warpNodeGrid((N_NODES * 32 + TPB - 1) / TPB);

    // ---- fork: CSR build on s2, concurrent with GEMM1/GEMM2 on main stream ----
    cudaEventRecord(evF, 0);
    cudaStreamWaitEvent(s2, evF, 0);

    zero_deg_kernel<<<nodeGrid, TPB, 0, s2>>>();
    hist_kernel<<<edgeGrid, TPB, 0, s2>>>(dst);
    scan1_kernel<<<SCAN_BLOCKS, SCAN_TPB, 0, s2>>>();
    scan2_kernel<<<1, 32, 0, s2>>>();
    scan3_kernel<<<SCAN_BLOCKS, SCAN_TPB, 0, s2>>>();
    fill_kernel<<<edgeGrid, TPB, 0, s2>>>(src, dst);
    cudaEventRecord(evJ, s2);

    // main stream: GEMMs that don't need the graph
    // h0 = relu(x @ W_in + b_in)            -> buf0
    gemm_kernel<<<gemmGrid, 256>>>(x, W_in, b_in, buf0, N_NODES, D_IN, 1);
    // xw1 = h0 @ W1                          -> buf1
    gemm_kernel<<<gemmGrid, 256>>>(buf0, W1, nullptr, buf1, N_NODES, HID, 0);

    // ---- join before first aggregation ----
    cudaStreamWaitEvent(0, evJ, 0);

    // h1 = relu(agg(xw1) + b1)               -> buf2
    agg_kernel<<<warpNodeGrid, TPB>>>(buf1, b1, buf2);
    // xw2 = h1 @ W2                          -> buf0
    gemm_kernel<<<gemmGrid, 256>>>(buf2, W2, nullptr, buf0, N_NODES, HID, 0);
    // h2 = relu(agg(xw2) + b2)               -> buf1
    agg_kernel<<<warpNodeGrid, TPB>>>(buf0, b2, buf1);
    // A = h2 @ Wm1[:128] + bm1               -> buf0
    gemm_kernel<<<gemmGrid, 256>>>(buf1, Wm1, bm1, buf0, N_NODES, HID, 0);
    // B = h2 @ Wm1[128:]                     -> buf2
    gemm_kernel<<<gemmGrid, 256>>>(buf1, Wm1 + HID * HID, nullptr, buf2, N_NODES, HID, 0);
    // logits per edge (CSR-grouped by dst)
    edge_kernel<<<warpNodeGrid, TPB>>>(buf0, buf2, Wm2, bm2, out);
}

// round 4
// speedup vs baseline: 1.9188x; 1.5317x over previous
#include <cuda_runtime.h>
#include <cstdint>

#define N_NODES 50000
#define N_EDGES 800000
#define D_IN 96
#define HID 128
#define SCAN_TPB 1024
#define SCAN_BLOCKS ((N_NODES + SCAN_TPB - 1) / SCAN_TPB)   // 49

// ---------------- scratch (device globals; no allocation allowed) ----------------
__device__ __align__(16) float g_buf0[N_NODES * HID];
__device__ __align__(16) float g_buf1[N_NODES * HID];
__device__ __align__(16) float g_buf2[N_NODES * HID];
__device__ float g_dinv[N_NODES];
__device__ int   g_deg[N_NODES];
__device__ int   g_rowptr[N_NODES + 1];
__device__ int   g_cursor[N_NODES];
__device__ int   g_partials[SCAN_BLOCKS + 1];
__device__ int   g_csr_src[N_EDGES];
__device__ int   g_csr_eid[N_EDGES];
__device__ float g_csr_norm[N_EDGES];

// ---------------- graph preprocessing ----------------
__global__ void zero_deg_kernel() {
    int i = blockIdx.x * blockDim.x + threadIdx.x;
    if (i < N_NODES) g_deg[i] = 0;
}

__global__ void hist_kernel(const int* __restrict__ dst) {
    int e = blockIdx.x * blockDim.x + threadIdx.x;
    if (e < N_EDGES) atomicAdd(&g_deg[dst[e]], 1);
}

__global__ void scan1_kernel() {
    __shared__ int ws[32];
    int gid = blockIdx.x * SCAN_TPB + threadIdx.x;
    int lane = threadIdx.x & 31, wid = threadIdx.x >> 5;
    int v = (gid < N_NODES) ? g_deg[gid] : 0;
    if (gid < N_NODES) g_dinv[gid] = rsqrtf((float)(v + 1));  // +1 self loop
    int x = v;
    #pragma unroll
    for (int off = 1; off < 32; off <<= 1) {
        int t = __shfl_up_sync(0xffffffff, x, off);
        if (lane >= off) x += t;
    }
    if (lane == 31) ws[wid] = x;
    __syncthreads();
    if (wid == 0) {
        int t = ws[lane];
        #pragma unroll
        for (int off = 1; off < 32; off <<= 1) {
            int u = __shfl_up_sync(0xffffffff, t, off);
            if (lane >= off) t += u;
        }
        ws[lane] = t;
    }
    __syncthreads();
    int excl = (wid ? ws[wid - 1] : 0) + x - v;
    if (gid < N_NODES) g_rowptr[gid] = excl;
    if (threadIdx.x == 0) g_partials[blockIdx.x] = ws[31];
}

// warp-parallel scan of SCAN_BLOCKS (=49) block sums
__global__ void scan2_kernel() {
    int lane = threadIdx.x;
    int v0 = (lane < SCAN_BLOCKS) ? g_partials[lane] : 0;
    int v1 = (lane + 32 < SCAN_BLOCKS) ? g_partials[lane + 32] : 0;
    int x0 = v0;
    #pragma unroll
    for (int off = 1; off < 32; off <<= 1) {
        int t = __shfl_up_sync(0xffffffff, x0, off);
        if (lane >= off) x0 += t;
    }
    int tot0 = __shfl_sync(0xffffffff, x0, 31);
    int x1 = v1;
    #pragma unroll
    for (int off = 1; off < 32; off <<= 1) {
        int t = __shfl_up_sync(0xffffffff, x1, off);
        if (lane >= off) x1 += t;
    }
    if (lane < SCAN_BLOCKS) g_partials[lane] = x0 - v0;
    if (lane + 32 < SCAN_BLOCKS) g_partials[lane + 32] = tot0 + x1 - v1;
    if (lane == 31) g_rowptr[N_NODES] = tot0 + __shfl_sync(0xffffffff, x1, 31);
}

__global__ void scan3_kernel() {
    int gid = blockIdx.x * SCAN_TPB + threadIdx.x;
    if (gid < N_NODES) {
        int r = g_rowptr[gid] + g_partials[blockIdx.x];
        g_rowptr[gid] = r;
        g_cursor[gid] = r;
    }
}

__global__ void fill_kernel(const int* __restrict__ src, const int* __restrict__ dst) {
    int e = blockIdx.x * blockDim.x + threadIdx.x;
    if (e < N_EDGES) {
        int s = src[e], d = dst[e];
        int p = atomicAdd(&g_cursor[d], 1);
        g_csr_src[p]  = s;
        g_csr_eid[p]  = e;
        g_csr_norm[p] = g_dinv[s] * g_dinv[d];
    }
}

// ---------------- tf32 mma.sync GEMM: C[M,128] = act(A[M,K] @ W[K,128] (+bias)) ----------------
__device__ __forceinline__ uint32_t cvt_tf32(float f) {
    uint32_t r;
    asm("cvt.rna.tf32.f32 %0, %1;" : "=r"(r) : "f"(f));
    return r;
}

#define MMA_TF32(c, a, b)                                                      \
    asm volatile(                                                              \
        "mma.sync.aligned.m16n8k8.row.col.f32.tf32.tf32.f32 "                  \
        "{%0,%1,%2,%3}, {%4,%5,%6,%7}, {%8,%9}, {%0,%1,%2,%3};"                \
        : "+f"((c)[0]), "+f"((c)[1]), "+f"((c)[2]), "+f"((c)[3])               \
        : "r"((a)[0]), "r"((a)[1]), "r"((a)[2]), "r"((a)[3]),                  \
          "r"((b)[0]), "r"((b)[1]))

// Block tile 128x128, BK=32, 256 threads = 8 warps, warp tile 32(M) x 64(N).
// As: [128][36] (A rows, tf32), stride 36 -> bank = row*4+k, conflict-free A frags.
// Bs: [32][136] (W rows k, cols n), stride 136 -> bank = k*8+n, conflict-free B frags.
template <int K>
__global__ void __launch_bounds__(256, 2) gemm_mma_kernel(
    const float* __restrict__ A, const float* __restrict__ W,
    const float* __restrict__ bias, float* __restrict__ C,
    int M, int do_relu)
{
    __shared__ uint32_t As[128 * 36];
    __shared__ uint32_t Bs[32 * 136];
    const int tid = threadIdx.x;
    const int lane = tid & 31, wid = tid >> 5;
    const int gID = lane >> 2, t4 = lane & 3;
    const int wm = wid & 3, wn = wid >> 2;
    const int m0 = blockIdx.x * 128;

    float acc[2][8][4];
    #pragma unroll
    for (int mi = 0; mi < 2; mi++)
        #pragma unroll
        for (int ni = 0; ni < 8; ni++)
            #pragma unroll
            for (int j = 0; j < 4; j++) acc[mi][ni][j] = 0.f;

    for (int k0 = 0; k0 < K; k0 += 32) {
        // A chunk: 128 rows x 32 cols (1024 float4 across 256 threads)
        #pragma unroll
        for (int i = 0; i < 4; i++) {
            int idx = tid + i * 256;
            int row = idx >> 3;
            int cf  = (idx & 7) * 4;
            int g = m0 + row;
            float4 v = make_float4(0.f, 0.f, 0.f, 0.f);
            if (g < M) v = *(const float4*)&A[(long)g * K + k0 + cf];
            uint32_t* p = &As[row * 36 + cf];
            p[0] = cvt_tf32(v.x); p[1] = cvt_tf32(v.y);
            p[2] = cvt_tf32(v.z); p[3] = cvt_tf32(v.w);
        }
        // W chunk: 32 rows (k) x 128 cols (n)
        #pragma unroll
        for (int i = 0; i < 4; i++) {
            int idx = tid + i * 256;
            int row = idx >> 5;
            int cf  = (idx & 31) * 4;
            float4 v = *(const float4*)&W[(long)(k0 + row) * 128 + cf];
            uint32_t* p = &Bs[row * 136 + cf];
            p[0] = cvt_tf32(v.x); p[1] = cvt_tf32(v.y);
            p[2] = cvt_tf32(v.z); p[3] = cvt_tf32(v.w);
        }
        __syncthreads();

        #pragma unroll
        for (int ks = 0; ks < 4; ks++) {
            uint32_t a[2][4], b[8][2];
            #pragma unroll
            for (int mi = 0; mi < 2; mi++) {
                int r = wm * 32 + mi * 16 + gID;
                int c = ks * 8 + t4;
                a[mi][0] = As[r * 36 + c];
                a[mi][1] = As[(r + 8) * 36 + c];
                a[mi][2] = As[r * 36 + c + 4];
                a[mi][3] = As[(r + 8) * 36 + c + 4];
            }
            #pragma unroll
            for (int ni = 0; ni < 8; ni++) {
                int n  = wn * 64 + ni * 8 + gID;
                int kk = ks * 8 + t4;
                b[ni][0] = Bs[kk * 136 + n];
                b[ni][1] = Bs[(kk + 4) * 136 + n];
            }
            #pragma unroll
            for (int mi = 0; mi < 2; mi++)
                #pragma unroll
                for (int ni = 0; ni < 8; ni++)
                    MMA_TF32(acc[mi][ni], a[mi], b[ni]);
        }
        __syncthreads();
    }

    // epilogue
    #pragma unroll
    for (int mi = 0; mi < 2; mi++) {
        int row = m0 + wm * 32 + mi * 16 + gID;
        #pragma unroll
        for (int ni = 0; ni < 8; ni++) {
            int col = wn * 64 + ni * 8 + t4 * 2;
            float bx = 0.f, by = 0.f;
            if (bias) { bx = bias[col]; by = bias[col + 1]; }
            float2 v0 = make_float2(acc[mi][ni][0] + bx, acc[mi][ni][1] + by);
            float2 v1 = make_float2(acc[mi][ni][2] + bx, acc[mi][ni][3] + by);
            if (do_relu) {
                v0.x = fmaxf(v0.x, 0.f); v0.y = fmaxf(v0.y, 0.f);
                v1.x = fmaxf(v1.x, 0.f); v1.y = fmaxf(v1.y, 0.f);
            }
            if (row < M)     *(float2*)&C[(long)row * 128 + col]       = v0;
            if (row + 8 < M) *(float2*)&C[(long)(row + 8) * 128 + col] = v1;
        }
    }
}

// ---------------- GCN aggregation: warp per node, gather over CSR ----------------
__global__ void agg_kernel(const float* __restrict__ xw, const float* __restrict__ bias,
                           float* __restrict__ out) {
    int warp = (blockIdx.x * blockDim.x + threadIdx.x) >> 5;
    int lane = threadIdx.x & 31;
    if (warp >= N_NODES) return;
    const float4* xw4 = (const float4*)xw;
    float di = g_dinv[warp];
    float sl = di * di;
    float4 v = xw4[warp * 32 + lane];
    float4 acc = make_float4(v.x * sl, v.y * sl, v.z * sl, v.w * sl);
    int p    = g_rowptr[warp];
    int pend = g_rowptr[warp + 1];
    for (; p < pend; p++) {
        int s = g_csr_src[p];
        float nm = g_csr_norm[p];
        float4 u = xw4[s * 32 + lane];
        acc.x += u.x * nm; acc.y += u.y * nm;
        acc.z += u.z * nm; acc.w += u.w * nm;
    }
    float4 b = ((const float4*)bias)[lane];
    acc.x = fmaxf(acc.x + b.x, 0.f);
    acc.y = fmaxf(acc.y + b.y, 0.f);
    acc.z = fmaxf(acc.z + b.z, 0.f);
    acc.w = fmaxf(acc.w + b.w, 0.f);
    ((float4*)out)[warp * 32 + lane] = acc;
}

// ---------------- edge MLP: warp per dst-node over CSR; B[d] stays in registers ----------------
__global__ void edge_kernel(const float* __restrict__ Aarr, const float* __restrict__ Barr,
                            const float* __restrict__ Wm2, const float* __restrict__ bm2,
                            float* __restrict__ out) {
    int node = (blockIdx.x * blockDim.x + threadIdx.x) >> 5;
    int lane = threadIdx.x & 31;
    if (node >= N_NODES) return;
    int p    = g_rowptr[node];
    int pend = g_rowptr[node + 1];
    if (p == pend) return;
    float4 b = ((const float4*)Barr)[node * 32 + lane];
    float4 w = ((const float4*)Wm2)[lane];
    float bm = bm2[0];
    for (; p < pend; p++) {
        int s   = g_csr_src[p];
        int eid = g_csr_eid[p];
        float4 a = ((const float4*)Aarr)[s * 32 + lane];
        float sum = fmaxf(a.x + b.x, 0.f) * w.x
                  + fmaxf(a.y + b.y, 0.f) * w.y
                  + fmaxf(a.z + b.z, 0.f) * w.z
                  + fmaxf(a.w + b.w, 0.f) * w.w;
        #pragma unroll
        for (int off = 16; off > 0; off >>= 1)
            sum += __shfl_down_sync(0xffffffff, sum, off);
        if (lane == 0) out[eid] = sum + bm;
    }
}

// ---------------- launch ----------------
extern "C" void kernel_launch(void* const* d_in, const int* in_sizes, int n_in,
                              void* d_out, int out_size) {
    const float* x      = (const float*)d_in[0];
    const int*   eidx   = (const int*)d_in[1];
    const float* W_in   = (const float*)d_in[2];
    const float* b_in   = (const float*)d_in[3];
    const float* W1     = (const float*)d_in[4];
    const float* b1     = (const float*)d_in[5];
    const float* W2     = (const float*)d_in[6];
    const float* b2     = (const float*)d_in[7];
    const float* Wm1    = (const float*)d_in[8];
    const float* bm1    = (const float*)d_in[9];
    const float* Wm2    = (const float*)d_in[10];
    const float* bm2    = (const float*)d_in[11];
    float* out = (float*)d_out;

    const int* src = eidx;
    const int* dst = eidx + N_EDGES;

    float *buf0, *buf1, *buf2;
    cudaGetSymbolAddress((void**)&buf0, g_buf0);
    cudaGetSymbolAddress((void**)&buf1, g_buf1);
    cudaGetSymbolAddress((void**)&buf2, g_buf2);

    static cudaStream_t s2 = nullptr;
    static cudaEvent_t evF = nullptr, evJ = nullptr;
    if (!s2) {
        cudaStreamCreateWithFlags(&s2, cudaStreamNonBlocking);
        cudaEventCreateWithFlags(&evF, cudaEventDisableTiming);
        cudaEventCreateWithFlags(&evJ, cudaEventDisableTiming);
    }

    const int TPB = 256;
    dim3 nodeGrid((N_NODES + TPB - 1) / TPB);
    dim3 edgeGrid((N_EDGES + TPB - 1) / TPB);
    dim3 gemmGrid((N_NODES + 127) / 128);
    dim3 warpNodeGrid((N_NODES * 32 + TPB - 1) / TPB);

    // ---- fork: CSR build on s2, concurrent with GEMM1/GEMM2 ----
    cudaEventRecord(evF, 0);
    cudaStreamWaitEvent(s2, evF, 0);

    zero_deg_kernel<<<nodeGrid, TPB, 0, s2>>>();
    hist_kernel<<<edgeGrid, TPB, 0, s2>>>(dst);
    scan1_kernel<<<SCAN_BLOCKS, SCAN_TPB, 0, s2>>>();
    scan2_kernel<<<1, 32, 0, s2>>>();
    scan3_kernel<<<SCAN_BLOCKS, SCAN_TPB, 0, s2>>>();
    fill_kernel<<<edgeGrid, TPB, 0, s2>>>(src, dst);
    cudaEventRecord(evJ, s2);

    // main stream: GEMMs that don't need the graph
    // h0 = relu(x @ W_in + b_in)            -> buf0
    gemm_mma_kernel<96><<<gemmGrid, 256>>>(x, W_in, b_in, buf0, N_NODES, 1);
    // xw1 = h0 @ W1                          -> buf1
    gemm_mma_kernel<128><<<gemmGrid, 256>>>(buf0, W1, nullptr, buf1, N_NODES, 0);

    // ---- join before first aggregation ----
    cudaStreamWaitEvent(0, evJ, 0);

    // h1 = relu(agg(xw1) + b1)               -> buf2
    agg_kernel<<<warpNodeGrid, TPB>>>(buf1, b1, buf2);
    // xw2 = h1 @ W2                          -> buf0
    gemm_mma_kernel<128><<<gemmGrid, 256>>>(buf2, W2, nullptr, buf0, N_NODES, 0);
    // h2 = relu(agg(xw2) + b2)               -> buf1
    agg_kernel<<<warpNodeGrid, TPB>>>(buf0, b2, buf1);
    // A = h2 @ Wm1[:128] + bm1               -> buf0
    gemm_mma_kernel<128><<<gemmGrid, 256>>>(buf1, Wm1, bm1, buf0, N_NODES, 0);
    // B = h2 @ Wm1[128:]                     -> buf2
    gemm_mma_kernel<128><<<gemmGrid, 256>>>(buf1, Wm1 + HID * HID, nullptr, buf2, N_NODES, 0);
    // logits per edge (CSR-grouped by dst)
    edge_kernel<<<warpNodeGrid, TPB>>>(buf0, buf2, Wm2, bm2, out);
}

// round 5
// speedup vs baseline: 2.0063x; 1.0456x over previous
#include <cuda_runtime.h>
#include <cstdint>

#define N_NODES 50000
#define N_EDGES 800000
#define D_IN 96
#define HID 128
#define SCAN_TPB 1024
#define SCAN_BLOCKS ((N_NODES + SCAN_TPB - 1) / SCAN_TPB)   // 49

// ---------------- scratch (device globals; no allocation allowed) ----------------
__device__ __align__(16) float g_buf0[N_NODES * HID];
__device__ __align__(16) float g_buf1[N_NODES * HID];
__device__ __align__(16) float g_buf2[N_NODES * HID];
__device__ float g_dinv[N_NODES];
__device__ int   g_deg[N_NODES];
__device__ int   g_rowptr[N_NODES + 1];
__device__ int   g_cursor[N_NODES];
__device__ int   g_partials[SCAN_BLOCKS + 1];
__device__ __align__(8) int2 g_csr_sn[N_EDGES];   // .x = src, .y = norm (float bits)
__device__ __align__(8) int2 g_csr_se[N_EDGES];   // .x = src, .y = edge id

// ---------------- graph preprocessing ----------------
__global__ void zero_deg_kernel() {
    int i = blockIdx.x * blockDim.x + threadIdx.x;
    if (i < N_NODES) g_deg[i] = 0;
}

__global__ void hist_kernel(const int* __restrict__ dst) {
    int e = blockIdx.x * blockDim.x + threadIdx.x;
    if (e < N_EDGES) atomicAdd(&g_deg[dst[e]], 1);
}

__global__ void scan1_kernel() {
    __shared__ int ws[32];
    int gid = blockIdx.x * SCAN_TPB + threadIdx.x;
    int lane = threadIdx.x & 31, wid = threadIdx.x >> 5;
    int v = (gid < N_NODES) ? g_deg[gid] : 0;
    if (gid < N_NODES) g_dinv[gid] = rsqrtf((float)(v + 1));  // +1 self loop
    int x = v;
    #pragma unroll
    for (int off = 1; off < 32; off <<= 1) {
        int t = __shfl_up_sync(0xffffffff, x, off);
        if (lane >= off) x += t;
    }
    if (lane == 31) ws[wid] = x;
    __syncthreads();
    if (wid == 0) {
        int t = ws[lane];
        #pragma unroll
        for (int off = 1; off < 32; off <<= 1) {
            int u = __shfl_up_sync(0xffffffff, t, off);
            if (lane >= off) t += u;
        }
        ws[lane] = t;
    }
    __syncthreads();
    int excl = (wid ? ws[wid - 1] : 0) + x - v;
    if (gid < N_NODES) g_rowptr[gid] = excl;
    if (threadIdx.x == 0) g_partials[blockIdx.x] = ws[31];
}

__global__ void scan2_kernel() {
    int lane = threadIdx.x;
    int v0 = (lane < SCAN_BLOCKS) ? g_partials[lane] : 0;
    int v1 = (lane + 32 < SCAN_BLOCKS) ? g_partials[lane + 32] : 0;
    int x0 = v0;
    #pragma unroll
    for (int off = 1; off < 32; off <<= 1) {
        int t = __shfl_up_sync(0xffffffff, x0, off);
        if (lane >= off) x0 += t;
    }
    int tot0 = __shfl_sync(0xffffffff, x0, 31);
    int x1 = v1;
    #pragma unroll
    for (int off = 1; off < 32; off <<= 1) {
        int t = __shfl_up_sync(0xffffffff, x1, off);
        if (lane >= off) x1 += t;
    }
    if (lane < SCAN_BLOCKS) g_partials[lane] = x0 - v0;
    if (lane + 32 < SCAN_BLOCKS) g_partials[lane + 32] = tot0 + x1 - v1;
    if (lane == 31) g_rowptr[N_NODES] = tot0 + __shfl_sync(0xffffffff, x1, 31);
}

__global__ void scan3_kernel() {
    int gid = blockIdx.x * SCAN_TPB + threadIdx.x;
    if (gid < N_NODES) {
        int r = g_rowptr[gid] + g_partials[blockIdx.x];
        g_rowptr[gid] = r;
        g_cursor[gid] = r;
    }
}

__global__ void fill_kernel(const int* __restrict__ src, const int* __restrict__ dst) {
    int e = blockIdx.x * blockDim.x + threadIdx.x;
    if (e < N_EDGES) {
        int s = src[e], d = dst[e];
        int p = atomicAdd(&g_cursor[d], 1);
        float nm = g_dinv[s] * g_dinv[d];
        g_csr_sn[p] = make_int2(s, __float_as_int(nm));
        g_csr_se[p] = make_int2(s, e);
    }
}

// ---------------- tf32 mma.sync GEMM, double-buffered ----------------
__device__ __forceinline__ uint32_t cvt_tf32(float f) {
    uint32_t r;
    asm("cvt.rna.tf32.f32 %0, %1;" : "=r"(r) : "f"(f));
    return r;
}

#define MMA_TF32(c, a, b)                                                      \
    asm volatile(                                                              \
        "mma.sync.aligned.m16n8k8.row.col.f32.tf32.tf32.f32 "                  \
        "{%0,%1,%2,%3}, {%4,%5,%6,%7}, {%8,%9}, {%0,%1,%2,%3};"                \
        : "+f"((c)[0]), "+f"((c)[1]), "+f"((c)[2]), "+f"((c)[3])               \
        : "r"((a)[0]), "r"((a)[1]), "r"((a)[2]), "r"((a)[3]),                  \
          "r"((b)[0]), "r"((b)[1]))

// Block tile 128x128, BK=16, 256 threads = 8 warps, warp tile 32(M) x 64(N).
// As: [2][128][20] tf32; Bs: [2][16][136].
// If W1 != nullptr: blockIdx.y selects (W0,bias0,C0) vs (W1,bias1,C1).
template <int K>
__global__ void __launch_bounds__(256, 2) gemm_mma_kernel(
    const float* __restrict__ A,
    const float* __restrict__ W0, const float* __restrict__ bias0, float* __restrict__ C0,
    const float* __restrict__ W1, const float* __restrict__ bias1, float* __restrict__ C1,
    int M, int do_relu)
{
    const float* W    = (blockIdx.y == 0) ? W0 : W1;
    const float* bias = (blockIdx.y == 0) ? bias0 : bias1;
    float*       C    = (blockIdx.y == 0) ? C0 : C1;

    __shared__ uint32_t As[2][128 * 20];
    __shared__ uint32_t Bs[2][16 * 136];
    const int tid = threadIdx.x;
    const int lane = tid & 31, wid = tid >> 5;
    const int gID = lane >> 2, t4 = lane & 3;
    const int wm = wid & 3, wn = wid >> 2;
    const int m0 = blockIdx.x * 128;
    constexpr int NC = K / 16;

    // per-thread load coordinates (2 float4 each for A and B per chunk)
    const int arow0 = tid >> 2;                 // 0..63
    const int acf   = (tid & 3) * 4;            // 0,4,8,12
    const int brow0 = tid >> 5;                 // 0..7
    const int bcf   = (tid & 31) * 4;           // 0..124

    float acc[2][8][4];
    #pragma unroll
    for (int mi = 0; mi < 2; mi++)
        #pragma unroll
        for (int ni = 0; ni < 8; ni++)
            #pragma unroll
            for (int j = 0; j < 4; j++) acc[mi][ni][j] = 0.f;

    float4 pa[2], pb[2];

    // prologue: load chunk 0
    {
        #pragma unroll
        for (int h = 0; h < 2; h++) {
            int g = m0 + arow0 + h * 64;
            pa[h] = make_float4(0.f, 0.f, 0.f, 0.f);
            if (g < M) pa[h] = *(const float4*)&A[(long)g * K + acf];
            pb[h] = *(const float4*)&W[(long)(brow0 + h * 8) * 128 + bcf];
        }
        #pragma unroll
        for (int h = 0; h < 2; h++) {
            uint32_t* p = &As[0][(arow0 + h * 64) * 20 + acf];
            p[0] = cvt_tf32(pa[h].x); p[1] = cvt_tf32(pa[h].y);
            p[2] = cvt_tf32(pa[h].z); p[3] = cvt_tf32(pa[h].w);
            uint32_t* q = &Bs[0][(brow0 + h * 8) * 136 + bcf];
            q[0] = cvt_tf32(pb[h].x); q[1] = cvt_tf32(pb[h].y);
            q[2] = cvt_tf32(pb[h].z); q[3] = cvt_tf32(pb[h].w);
        }
    }
    __syncthreads();

    #pragma unroll
    for (int c = 0; c < NC; c++) {
        const int cur = c & 1, nxt = cur ^ 1;
        // issue global loads for next chunk early (latency hidden by compute)
        if (c + 1 < NC) {
            int k0 = (c + 1) * 16;
            #pragma unroll
            for (int h = 0; h < 2; h++) {
                int g = m0 + arow0 + h * 64;
                pa[h] = make_float4(0.f, 0.f, 0.f, 0.f);
                if (g < M) pa[h] = *(const float4*)&A[(long)g * K + k0 + acf];
                pb[h] = *(const float4*)&W[(long)(k0 + brow0 + h * 8) * 128 + bcf];
            }
        }
        // compute on current chunk: 2 ks steps
        #pragma unroll
        for (int ks = 0; ks < 2; ks++) {
            uint32_t a[2][4], b[8][2];
            #pragma unroll
            for (int mi = 0; mi < 2; mi++) {
                int r = wm * 32 + mi * 16 + gID;
                int cc = ks * 8 + t4;
                a[mi][0] = As[cur][r * 20 + cc];
                a[mi][1] = As[cur][(r + 8) * 20 + cc];
                a[mi][2] = As[cur][r * 20 + cc + 4];
                a[mi][3] = As[cur][(r + 8) * 20 + cc + 4];
            }
            #pragma unroll
            for (int ni = 0; ni < 8; ni++) {
                int n  = wn * 64 + ni * 8 + gID;
                int kk = ks * 8 + t4;
                b[ni][0] = Bs[cur][kk * 136 + n];
                b[ni][1] = Bs[cur][(kk + 4) * 136 + n];
            }
            #pragma unroll
            for (int mi = 0; mi < 2; mi++)
                #pragma unroll
                for (int ni = 0; ni < 8; ni++)
                    MMA_TF32(acc[mi][ni], a[mi], b[ni]);
        }
        if (c + 1 < NC) {
            #pragma unroll
            for (int h = 0; h < 2; h++) {
                uint32_t* p = &As[nxt][(arow0 + h * 64) * 20 + acf];
                p[0] = cvt_tf32(pa[h].x); p[1] = cvt_tf32(pa[h].y);
                p[2] = cvt_tf32(pa[h].z); p[3] = cvt_tf32(pa[h].w);
                uint32_t* q = &Bs[nxt][(brow0 + h * 8) * 136 + bcf];
                q[0] = cvt_tf32(pb[h].x); q[1] = cvt_tf32(pb[h].y);
                q[2] = cvt_tf32(pb[h].z); q[3] = cvt_tf32(pb[h].w);
            }
            __syncthreads();
        }
    }

    // epilogue
    #pragma unroll
    for (int mi = 0; mi < 2; mi++) {
        int row = m0 + wm * 32 + mi * 16 + gID;
        #pragma unroll
        for (int ni = 0; ni < 8; ni++) {
            int col = wn * 64 + ni * 8 + t4 * 2;
            float bx = 0.f, by = 0.f;
            if (bias) { bx = bias[col]; by = bias[col + 1]; }
            float2 v0 = make_float2(acc[mi][ni][0] + bx, acc[mi][ni][1] + by);
            float2 v1 = make_float2(acc[mi][ni][2] + bx, acc[mi][ni][3] + by);
            if (do_relu) {
                v0.x = fmaxf(v0.x, 0.f); v0.y = fmaxf(v0.y, 0.f);
                v1.x = fmaxf(v1.x, 0.f); v1.y = fmaxf(v1.y, 0.f);
            }
            if (row < M)     *(float2*)&C[(long)row * 128 + col]       = v0;
            if (row + 8 < M) *(float2*)&C[(long)(row + 8) * 128 + col] = v1;
        }
    }
}

// ---------------- GCN aggregation: warp per node, gather over CSR ----------------
__global__ void agg_kernel(const float* __restrict__ xw, const float* __restrict__ bias,
                           float* __restrict__ out) {
    int warp = (blockIdx.x * blockDim.x + threadIdx.x) >> 5;
    int lane = threadIdx.x & 31;
    if (warp >= N_NODES) return;
    const float4* xw4 = (const float4*)xw;
    float di = g_dinv[warp];
    float sl = di * di;
    float4 v = xw4[warp * 32 + lane];
    float4 acc = make_float4(v.x * sl, v.y * sl, v.z * sl, v.w * sl);
    int p    = g_rowptr[warp];
    int pend = g_rowptr[warp + 1];
    for (; p < pend; p++) {
        int2 sn = g_csr_sn[p];
        float nm = __int_as_float(sn.y);
        float4 u = xw4[sn.x * 32 + lane];
        acc.x += u.x * nm; acc.y += u.y * nm;
        acc.z += u.z * nm; acc.w += u.w * nm;
    }
    float4 b = ((const float4*)bias)[lane];
    acc.x = fmaxf(acc.x + b.x, 0.f);
    acc.y = fmaxf(acc.y + b.y, 0.f);
    acc.z = fmaxf(acc.z + b.z, 0.f);
    acc.w = fmaxf(acc.w + b.w, 0.f);
    ((float4*)out)[warp * 32 + lane] = acc;
}

// ---------------- edge MLP: warp per dst-node over CSR; B[d] stays in registers ----------------
__global__ void edge_kernel(const float* __restrict__ Aarr, const float* __restrict__ Barr,
                            const float* __restrict__ Wm2, const float* __restrict__ bm2,
                            float* __restrict__ out) {
    int node = (blockIdx.x * blockDim.x + threadIdx.x) >> 5;
    int lane = threadIdx.x & 31;
    if (node >= N_NODES) return;
    int p    = g_rowptr[node];
    int pend = g_rowptr[node + 1];
    if (p == pend) return;
    float4 b = ((const float4*)Barr)[node * 32 + lane];
    float4 w = ((const float4*)Wm2)[lane];
    float bm = bm2[0];
    for (; p < pend; p++) {
        int2 se = g_csr_se[p];
        float4 a = ((const float4*)Aarr)[se.x * 32 + lane];
        float sum = fmaxf(a.x + b.x, 0.f) * w.x
                  + fmaxf(a.y + b.y, 0.f) * w.y
                  + fmaxf(a.z + b.z, 0.f) * w.z
                  + fmaxf(a.w + b.w, 0.f) * w.w;
        #pragma unroll
        for (int off = 16; off > 0; off >>= 1)
            sum += __shfl_down_sync(0xffffffff, sum, off);
        if (lane == 0) out[se.y] = sum + bm;
    }
}

// ---------------- launch ----------------
extern "C" void kernel_launch(void* const* d_in, const int* in_sizes, int n_in,
                              void* d_out, int out_size) {
    const float* x      = (const float*)d_in[0];
    const int*   eidx   = (const int*)d_in[1];
    const float* W_in   = (const float*)d_in[2];
    const float* b_in   = (const float*)d_in[3];
    const float* W1     = (const float*)d_in[4];
    const float* b1     = (const float*)d_in[5];
    const float* W2     = (const float*)d_in[6];
    const float* b2     = (const float*)d_in[7];
    const float* Wm1    = (const float*)d_in[8];
    const float* bm1    = (const float*)d_in[9];
    const float* Wm2    = (const float*)d_in[10];
    const float* bm2    = (const float*)d_in[11];
    float* out = (float*)d_out;

    const int* src = eidx;
    const int* dst = eidx + N_EDGES;

    float *buf0, *buf1, *buf2;
    cudaGetSymbolAddress((void**)&buf0, g_buf0);
    cudaGetSymbolAddress((void**)&buf1, g_buf1);
    cudaGetSymbolAddress((void**)&buf2, g_buf2);

    static cudaStream_t s2 = nullptr;
    static cudaEvent_t evF = nullptr, evJ = nullptr;
    if (!s2) {
        cudaStreamCreateWithFlags(&s2, cudaStreamNonBlocking);
        cudaEventCreateWithFlags(&evF, cudaEventDisableTiming);
        cudaEventCreateWithFlags(&evJ, cudaEventDisableTiming);
    }

    const int TPB = 256;
    dim3 nodeGrid((N_NODES + TPB - 1) / TPB);
    dim3 edgeGrid((N_EDGES + TPB - 1) / TPB);
    dim3 gemmGrid((N_NODES + 127) / 128, 1);
    dim3 gemmGrid2((N_NODES + 127) / 128, 2);
    dim3 warpNodeGrid((N_NODES * 32 + TPB - 1) / TPB);

    // ---- fork: CSR build on s2, concurrent with GEMM1/GEMM2 ----
    cudaEventRecord(evF, 0);
    cudaStreamWaitEvent(s2, evF, 0);

    zero_deg_kernel<<<nodeGrid, TPB, 0, s2>>>();
    hist_kernel<<<edgeGrid, TPB, 0, s2>>>(dst);
    scan1_kernel<<<SCAN_BLOCKS, SCAN_TPB, 0, s2>>>();
    scan2_kernel<<<1, 32, 0, s2>>>();
    scan3_kernel<<<SCAN_BLOCKS, SCAN_TPB, 0, s2>>>();
    fill_kernel<<<edgeGrid, TPB, 0, s2>>>(src, dst);
    cudaEventRecord(evJ, s2);

    // main stream: GEMMs that don't need the graph
    // h0 = relu(x @ W_in + b_in)            -> buf0
    gemm_mma_kernel<96><<<gemmGrid, 256>>>(x, W_in, b_in, buf0,
                                           nullptr, nullptr, nullptr, N_NODES, 1);
    // xw1 = h0 @ W1                          -> buf1
    gemm_mma_kernel<128><<<gemmGrid, 256>>>(buf0, W1, nullptr, buf1,
                                            nullptr, nullptr, nullptr, N_NODES, 0);

    // ---- join before first aggregation ----
    cudaStreamWaitEvent(0, evJ, 0);

    // h1 = relu(agg(xw1) + b1)               -> buf2
    agg_kernel<<<warpNodeGrid, TPB>>>(buf1, b1, buf2);
    // xw2 = h1 @ W2                          -> buf0
    gemm_mma_kernel<128><<<gemmGrid, 256>>>(buf2, W2, nullptr, buf0,
                                            nullptr, nullptr, nullptr, N_NODES, 0);
    // h2 = relu(agg(xw2) + b2)               -> buf1
    agg_kernel<<<warpNodeGrid, TPB>>>(buf0, b2, buf1);
    // A = h2 @ Wm1[:128] + bm1 -> buf0;  B = h2 @ Wm1[128:] -> buf2  (one launch)
    gemm_mma_kernel<128><<<gemmGrid2, 256>>>(buf1, Wm1, bm1, buf0,
                                             Wm1 + HID * HID, nullptr, buf2, N_NODES, 0);
    // logits per edge (CSR-grouped by dst)
    edge_kernel<<<warpNodeGrid, TPB>>>(buf0, buf2, Wm2, bm2, out);
}